// round 14
// baseline (speedup 1.0000x reference)
#include <cuda_runtime.h>

#define IN_F   4096
#define OUT_F  11008
#define NC     16
#define TOPK   1024

__device__ float g_masks[NC * IN_F];   // per-center masked-x candidates
__device__ float g_d2[NC];

// ---------------------------------------------------------------------------
// Kernel 1: 16 blocks x 1024 threads, fully independent (no inter-block sync).
// PDL trigger at ENTRY (all threads) -> matvec grid launches immediately and
// prefetches W into L2 for the whole duration of this kernel.
// Block c: softmax(|x|) (no max-subtraction; feeds only the argmin),
// d2 -> g_d2[c], exact top-1024 select of center c -> g_masks[c].
// ---------------------------------------------------------------------------
__global__ void __launch_bounds__(1024)
prep_kernel(const float* __restrict__ x,
            const float* __restrict__ centers)
{
    // earliest legal trigger point; dependent kernel still waits for FULL
    // grid completion at its cudaGridDependencySynchronize().
    cudaTriggerProgrammaticLaunchCompletion();

    __shared__ float    s_red[32];
    __shared__ float    s_b;
    __shared__ unsigned s_hist[4][256];
    __shared__ unsigned s_wsum[8];
    __shared__ int      s_ints[2];    // [0]=remaining [1]=prefix
    __shared__ int      s_warp[32];

    const int tid  = threadIdx.x;
    const int lane = tid & 31;
    const int wid  = tid >> 5;
    const int c    = blockIdx.x;

    ((unsigned*)s_hist)[tid] = 0u;    // clear all 4 histograms (1 entry/thread)

    // ---- loads (independent, issued together) ----
    const float4 xv = reinterpret_cast<const float4*>(x)[tid];
    const float4 cv = reinterpret_cast<const float4*>(centers)[c * (IN_F / 4) + tid];

    // ---- softmax(|x|) without max-subtraction:
    //      exp(a)/sum == exp(a-m)/sum(exp(a-m)); |x| small so no overflow.
    //      Feeds ONLY the d2 argmin (margins >> rounding). ----
    float e[4] = { expf(fabsf(xv.x)), expf(fabsf(xv.y)),
                   expf(fabsf(xv.z)), expf(fabsf(xv.w)) };
    float s = e[0] + e[1] + e[2] + e[3];
#pragma unroll
    for (int o = 16; o > 0; o >>= 1) s += __shfl_xor_sync(0xffffffffu, s, o);
    if (lane == 0) s_red[wid] = s;
    __syncthreads();
    if (wid == 0) {
        float r = s_red[lane];
#pragma unroll
        for (int o = 16; o > 0; o >>= 1) r += __shfl_xor_sync(0xffffffffu, r, o);
        if (lane == 0) s_b = r;
    }
    __syncthreads();
    const float inv_s = 1.f / s_b;

    // ---- d2 to center c ----
    float dx = cv.x - e[0] * inv_s;
    float dy = cv.y - e[1] * inv_s;
    float dz = cv.z - e[2] * inv_s;
    float dw = cv.w - e[3] * inv_s;
    float d2 = dx * dx + dy * dy + dz * dz + dw * dw;
#pragma unroll
    for (int o = 16; o > 0; o >>= 1) d2 += __shfl_xor_sync(0xffffffffu, d2, o);
    __syncthreads();
    if (lane == 0) s_red[wid] = d2;
    __syncthreads();
    if (tid == 0) {
        float r = 0.f;
#pragma unroll
        for (int w = 0; w < 32; w++) r += s_red[w];
        g_d2[c] = r;
    }

    // ---- local exact top-1024 select of center c (keys in registers) ----
    const unsigned key[4] = { __float_as_uint(cv.x), __float_as_uint(cv.y),
                              __float_as_uint(cv.z), __float_as_uint(cv.w) };

    unsigned prefix    = 0;
    int      remaining = TOPK;
#pragma unroll
    for (int p = 0; p < 4; p++) {
        const int shift = 24 - 8 * p;
#pragma unroll
        for (int j = 0; j < 4; j++) {
            bool match = (p == 0) ||
                         ((key[j] >> (shift + 8)) == (prefix >> (shift + 8)));
            if (match) atomicAdd(&s_hist[p][(key[j] >> shift) & 255u], 1u);
        }
        __syncthreads();
        unsigned v = 0, cnt = 0;
        if (tid < 256) {
            cnt = s_hist[p][tid];
            v = cnt;
#pragma unroll
            for (int off = 1; off < 32; off <<= 1) {
                unsigned n = __shfl_down_sync(0xffffffffu, v, off);
                if (lane + off < 32) v += n;
            }
            if (lane == 0) s_wsum[wid] = v;
        }
        __syncthreads();
        if (tid < 256) {
            unsigned off = 0;
            for (int w2 = wid + 1; w2 < 8; w2++) off += s_wsum[w2];
            unsigned ge = v + off;             // #keys byte >= tid (among matching)
            unsigned gt = ge - cnt;            // #keys byte >  tid
            if ((int)ge >= remaining && (int)gt < remaining) {   // unique crossing
                s_ints[0] = remaining - (int)gt;
                s_ints[1] = (int)(prefix | ((unsigned)tid << shift));
            }
        }
        __syncthreads();
        remaining = s_ints[0];
        prefix    = (unsigned)s_ints[1];
        __syncthreads();
    }
    const unsigned T = prefix;
    const int      R = remaining;              // R lowest-index ties (jax order)

    // tie-rank prefix scan (index order)
    int cnt4[4];
    int tot = 0;
#pragma unroll
    for (int j = 0; j < 4; j++) {
        cnt4[j] = tot;
        tot += (key[j] == T) ? 1 : 0;
    }
    int incl = tot;
#pragma unroll
    for (int off = 1; off < 32; off <<= 1) {
        int n = __shfl_up_sync(0xffffffffu, incl, off);
        if (lane >= off) incl += n;
    }
    if (lane == 31) s_warp[wid] = incl;
    __syncthreads();
    if (wid == 0) {
        int v = s_warp[lane];
#pragma unroll
        for (int off = 1; off < 32; off <<= 1) {
            int n = __shfl_up_sync(0xffffffffu, v, off);
            if (lane >= off) v += n;
        }
        s_warp[lane] = v;
    }
    __syncthreads();
    const int excl = incl - tot + (wid > 0 ? s_warp[wid - 1] : 0);
    const float xin[4] = { xv.x, xv.y, xv.z, xv.w };
    float o4[4];
#pragma unroll
    for (int j = 0; j < 4; j++) {
        bool sel = (key[j] > T) || (key[j] == T && (excl + cnt4[j]) < R);
        o4[j] = sel ? xin[j] : 0.f;
    }
    reinterpret_cast<float4*>(g_masks)[c * (IN_F / 4) + tid] =
        make_float4(o4[0], o4[1], o4[2], o4[3]);
}

// ---------------------------------------------------------------------------
// Kernel 2: out = W @ g_masks[argmin d2] + bias. R1's best-measured config
// (grid=1376, block=256, 1 row/warp, unroll 8). L2 prefetch + PDL sync, then
// per-block argmin (deterministic, identical in every block).
// ---------------------------------------------------------------------------
__global__ void __launch_bounds__(256)
matvec_kernel(const float* __restrict__ W,
              const float* __restrict__ bias,
              float* __restrict__ out)
{
    __shared__ float4 sx[IN_F / 4];
    __shared__ int    s_ci;
    const int tid  = threadIdx.x;
    const int warp = tid >> 5;
    const int lane = tid & 31;
    const int row  = blockIdx.x * 8 + warp;   // 11008 = 1376 * 8, in range

    const float4* wr = reinterpret_cast<const float4*>(W + (size_t)row * IN_F);

    // ---- L2 prefetch of this warp's first 2KB of W (runs during prep) ----
#pragma unroll
    for (int k = 0; k < 4; k++) {
        const float4* p = wr + lane + 32 * k;
        float pa, pb, pc, pd;
        asm volatile("ld.global.cg.v4.f32 {%0,%1,%2,%3}, [%4];"
                     : "=f"(pa), "=f"(pb), "=f"(pc), "=f"(pd)
                     : "l"(p));
    }

    // ---- wait for prep grid completion (memory visible); no-op if serial ----
    cudaGridDependencySynchronize();

    if (tid == 0) {
        int best = 0;
        float bv = g_d2[0];
#pragma unroll
        for (int k = 1; k < NC; k++)
            if (g_d2[k] < bv) { bv = g_d2[k]; best = k; }   // first-min tie-break
        s_ci = best;
    }
    __syncthreads();
    const float4* xm = reinterpret_cast<const float4*>(g_masks) + s_ci * (IN_F / 4);
    for (int i = tid; i < IN_F / 4; i += 256)
        sx[i] = xm[i];
    __syncthreads();

    float acc = 0.f;
#pragma unroll 8
    for (int j = lane; j < IN_F / 4; j += 32) {
        float4 w  = wr[j];
        float4 xv = sx[j];
        acc += w.x * xv.x + w.y * xv.y + w.z * xv.z + w.w * xv.w;
    }
#pragma unroll
    for (int o = 16; o > 0; o >>= 1)
        acc += __shfl_xor_sync(0xffffffffu, acc, o);
    if (lane == 0)
        out[row] = acc + bias[row];
}

// ---------------------------------------------------------------------------
extern "C" void kernel_launch(void* const* d_in, const int* in_sizes, int n_in,
                              void* d_out, int out_size)
{
    const float* x       = (const float*)d_in[0];  // [4096]
    const float* weight  = (const float*)d_in[1];  // [11008, 4096]
    const float* bias    = (const float*)d_in[2];  // [11008]
    const float* centers = (const float*)d_in[3];  // [16, 4096]
    float*       out     = (float*)d_out;          // [11008]

    prep_kernel<<<NC, 1024>>>(x, centers);

    // PDL launch: matvec begins (prefetching) while prep runs.
    cudaLaunchConfig_t cfg = {};
    cfg.gridDim  = dim3(OUT_F / 8);
    cfg.blockDim = dim3(256);
    cfg.stream   = 0;
    cudaLaunchAttribute attr[1];
    attr[0].id = cudaLaunchAttributeProgrammaticStreamSerialization;
    attr[0].val.programmaticStreamSerializationAllowed = 1;
    cfg.attrs    = attr;
    cfg.numAttrs = 1;
    cudaLaunchKernelEx(&cfg, matvec_kernel, weight, bias, out);
}

// round 15
// speedup vs baseline: 1.0265x; 1.0265x over previous
#include <cuda_runtime.h>

#define IN_F   4096
#define OUT_F  11008
#define NC     16
#define TOPK   1024

__device__ float g_masks[NC * IN_F];   // per-center masked-x candidates
__device__ float g_d2[NC];

// ---------------------------------------------------------------------------
// Kernel 1: 16 blocks x 1024 threads, fully independent (no inter-block sync).
// PDL trigger at entry -> matvec grid launches immediately and prefetches W
// into L2 for the whole duration of this kernel.
// Block c: softmax(|x|) (no max-subtraction; feeds only the argmin),
// d2 -> g_d2[c], exact top-1024 select of center c -> g_masks[c].
// ---------------------------------------------------------------------------
__global__ void __launch_bounds__(1024)
prep_kernel(const float* __restrict__ x,
            const float* __restrict__ centers)
{
    cudaTriggerProgrammaticLaunchCompletion();

    __shared__ float    s_red[32];
    __shared__ float    s_b;
    __shared__ unsigned s_hist[4][256];
    __shared__ unsigned s_wsum[8];
    __shared__ int      s_ints[2];    // [0]=remaining [1]=prefix
    __shared__ int      s_warp[32];

    const int tid  = threadIdx.x;
    const int lane = tid & 31;
    const int wid  = tid >> 5;
    const int c    = blockIdx.x;

    ((unsigned*)s_hist)[tid] = 0u;    // clear all 4 histograms (1 entry/thread)

    // ---- loads (independent, issued together) ----
    const float4 xv = reinterpret_cast<const float4*>(x)[tid];
    const float4 cv = reinterpret_cast<const float4*>(centers)[c * (IN_F / 4) + tid];

    // ---- softmax(|x|) without max-subtraction (feeds only the d2 argmin) ----
    float e[4] = { expf(fabsf(xv.x)), expf(fabsf(xv.y)),
                   expf(fabsf(xv.z)), expf(fabsf(xv.w)) };
    float s = e[0] + e[1] + e[2] + e[3];
#pragma unroll
    for (int o = 16; o > 0; o >>= 1) s += __shfl_xor_sync(0xffffffffu, s, o);
    if (lane == 0) s_red[wid] = s;
    __syncthreads();
    if (wid == 0) {
        float r = s_red[lane];
#pragma unroll
        for (int o = 16; o > 0; o >>= 1) r += __shfl_xor_sync(0xffffffffu, r, o);
        if (lane == 0) s_b = r;
    }
    __syncthreads();
    const float inv_s = 1.f / s_b;

    // ---- d2 to center c ----
    float dx = cv.x - e[0] * inv_s;
    float dy = cv.y - e[1] * inv_s;
    float dz = cv.z - e[2] * inv_s;
    float dw = cv.w - e[3] * inv_s;
    float d2 = dx * dx + dy * dy + dz * dz + dw * dw;
#pragma unroll
    for (int o = 16; o > 0; o >>= 1) d2 += __shfl_xor_sync(0xffffffffu, d2, o);
    __syncthreads();
    if (lane == 0) s_red[wid] = d2;
    __syncthreads();
    if (tid == 0) {
        float r = 0.f;
#pragma unroll
        for (int w = 0; w < 32; w++) r += s_red[w];
        g_d2[c] = r;
    }

    // ---- local exact top-1024 select of center c (keys in registers) ----
    const unsigned key[4] = { __float_as_uint(cv.x), __float_as_uint(cv.y),
                              __float_as_uint(cv.z), __float_as_uint(cv.w) };

    unsigned prefix    = 0;
    int      remaining = TOPK;
#pragma unroll
    for (int p = 0; p < 4; p++) {
        const int shift = 24 - 8 * p;
#pragma unroll
        for (int j = 0; j < 4; j++) {
            bool match = (p == 0) ||
                         ((key[j] >> (shift + 8)) == (prefix >> (shift + 8)));
            if (match) atomicAdd(&s_hist[p][(key[j] >> shift) & 255u], 1u);
        }
        __syncthreads();
        unsigned v = 0, cnt = 0;
        if (tid < 256) {
            cnt = s_hist[p][tid];
            v = cnt;
#pragma unroll
            for (int off = 1; off < 32; off <<= 1) {
                unsigned n = __shfl_down_sync(0xffffffffu, v, off);
                if (lane + off < 32) v += n;
            }
            if (lane == 0) s_wsum[wid] = v;
        }
        __syncthreads();
        if (tid < 256) {
            unsigned off = 0;
            for (int w2 = wid + 1; w2 < 8; w2++) off += s_wsum[w2];
            unsigned ge = v + off;             // #keys byte >= tid (among matching)
            unsigned gt = ge - cnt;            // #keys byte >  tid
            if ((int)ge >= remaining && (int)gt < remaining) {   // unique crossing
                s_ints[0] = remaining - (int)gt;
                s_ints[1] = (int)(prefix | ((unsigned)tid << shift));
            }
        }
        __syncthreads();
        remaining = s_ints[0];
        prefix    = (unsigned)s_ints[1];
        __syncthreads();
    }
    const unsigned T = prefix;
    const int      R = remaining;              // R lowest-index ties (jax order)

    // tie-rank prefix scan (index order)
    int cnt4[4];
    int tot = 0;
#pragma unroll
    for (int j = 0; j < 4; j++) {
        cnt4[j] = tot;
        tot += (key[j] == T) ? 1 : 0;
    }
    int incl = tot;
#pragma unroll
    for (int off = 1; off < 32; off <<= 1) {
        int n = __shfl_up_sync(0xffffffffu, incl, off);
        if (lane >= off) incl += n;
    }
    if (lane == 31) s_warp[wid] = incl;
    __syncthreads();
    if (wid == 0) {
        int v = s_warp[lane];
#pragma unroll
        for (int off = 1; off < 32; off <<= 1) {
            int n = __shfl_up_sync(0xffffffffu, v, off);
            if (lane >= off) v += n;
        }
        s_warp[lane] = v;
    }
    __syncthreads();
    const int excl = incl - tot + (wid > 0 ? s_warp[wid - 1] : 0);
    const float xin[4] = { xv.x, xv.y, xv.z, xv.w };
    float o4[4];
#pragma unroll
    for (int j = 0; j < 4; j++) {
        bool sel = (key[j] > T) || (key[j] == T && (excl + cnt4[j]) < R);
        o4[j] = sel ? xin[j] : 0.f;
    }
    reinterpret_cast<float4*>(g_masks)[c * (IN_F / 4) + tid] =
        make_float4(o4[0], o4[1], o4[2], o4[3]);
}

// ---------------------------------------------------------------------------
// Kernel 2: out = W @ g_masks[argmin d2] + bias. R1's best-measured config
// (grid=1376, block=256, 1 row/warp, unroll 8). Deep L2 prefetch (6KB/warp)
// + early bias load + PDL sync, then per-block argmin.
// ---------------------------------------------------------------------------
__global__ void __launch_bounds__(256)
matvec_kernel(const float* __restrict__ W,
              const float* __restrict__ bias,
              float* __restrict__ out)
{
    __shared__ float4 sx[IN_F / 4];
    __shared__ int    s_ci;
    const int tid  = threadIdx.x;
    const int warp = tid >> 5;
    const int lane = tid & 31;
    const int row  = blockIdx.x * 8 + warp;   // 11008 = 1376 * 8, in range

    const float4* wr = reinterpret_cast<const float4*>(W + (size_t)row * IN_F);

    // ---- early bias load (independent of prep) ----
    const float b = bias[row];

    // ---- deep L2 prefetch: first 6KB of this warp's row (runs during prep).
    //      Fire-and-forget: dead destinations, does not delay the sync. ----
#pragma unroll
    for (int k = 0; k < 12; k++) {
        const float4* p = wr + lane + 32 * k;
        float pa, pb, pc, pd;
        asm volatile("ld.global.cg.v4.f32 {%0,%1,%2,%3}, [%4];"
                     : "=f"(pa), "=f"(pb), "=f"(pc), "=f"(pd)
                     : "l"(p));
    }

    // ---- wait for prep grid completion (memory visible); no-op if serial ----
    cudaGridDependencySynchronize();

    if (tid == 0) {
        int best = 0;
        float bv = g_d2[0];
#pragma unroll
        for (int k = 1; k < NC; k++)
            if (g_d2[k] < bv) { bv = g_d2[k]; best = k; }   // first-min tie-break
        s_ci = best;
    }
    __syncthreads();
    const float4* xm = reinterpret_cast<const float4*>(g_masks) + s_ci * (IN_F / 4);
    for (int i = tid; i < IN_F / 4; i += 256)
        sx[i] = xm[i];
    __syncthreads();

    float acc = 0.f;
#pragma unroll 8
    for (int j = lane; j < IN_F / 4; j += 32) {
        float4 w  = wr[j];
        float4 xv = sx[j];
        acc += w.x * xv.x + w.y * xv.y + w.z * xv.z + w.w * xv.w;
    }
#pragma unroll
    for (int o = 16; o > 0; o >>= 1)
        acc += __shfl_xor_sync(0xffffffffu, acc, o);
    if (lane == 0)
        out[row] = acc + b;
}

// ---------------------------------------------------------------------------
extern "C" void kernel_launch(void* const* d_in, const int* in_sizes, int n_in,
                              void* d_out, int out_size)
{
    const float* x       = (const float*)d_in[0];  // [4096]
    const float* weight  = (const float*)d_in[1];  // [11008, 4096]
    const float* bias    = (const float*)d_in[2];  // [11008]
    const float* centers = (const float*)d_in[3];  // [16, 4096]
    float*       out     = (float*)d_out;          // [11008]

    prep_kernel<<<NC, 1024>>>(x, centers);

    // PDL launch: matvec begins (prefetching) while prep runs.
    cudaLaunchConfig_t cfg = {};
    cfg.gridDim  = dim3(OUT_F / 8);
    cfg.blockDim = dim3(256);
    cfg.stream   = 0;
    cudaLaunchAttribute attr[1];
    attr[0].id = cudaLaunchAttributeProgrammaticStreamSerialization;
    attr[0].val.programmaticStreamSerializationAllowed = 1;
    cfg.attrs    = attr;
    cfg.numAttrs = 1;
    cudaLaunchKernelEx(&cfg, matvec_kernel, weight, bias, out);
}